// round 14
// baseline (speedup 1.0000x reference)
#include <cuda_runtime.h>
#include <cuda_bf16.h>
#include <stdint.h>

#define NTOK 8192
#define DIM  1024
#define DK   128
#define DV   128

// ---------------- device globals (allocation-free scratch) ----------------
__device__ float g_v[NTOK * DV];
__device__ __align__(256) __nv_bfloat16 g_qkh[NTOK * DK];   // qk bf16 row-major
__device__ __align__(256) float g_ss[NTOK];                 // ||qk_i||^2 fp32
__device__ __align__(256) float g_O[2][NTOK * DV];          // split-KV numerators
__device__ __align__(256) float g_l[2][NTOK];               // split-KV denominators

// ---------------- helpers ----------------
__device__ __forceinline__ uint32_t smem_to_u32(const void* p) {
    uint32_t a;
    asm("{ .reg .u64 t; cvta.to.shared.u64 t, %1; cvt.u32.u64 %0, t; }" : "=r"(a) : "l"(p));
    return a;
}
__device__ __forceinline__ void cp16(uint32_t dst, const void* src) {
    asm volatile("cp.async.cg.shared.global [%0], [%1], 16;" :: "r"(dst), "l"(src) : "memory");
}
#define CP_COMMIT() asm volatile("cp.async.commit_group;" ::: "memory")
#define CP_WAIT0()  asm volatile("cp.async.wait_group 0;" ::: "memory")

__device__ __forceinline__ uint32_t bf2_to_u32(__nv_bfloat162 v) {
    uint32_t u; *(__nv_bfloat162*)&u = v; return u;
}

#define LDSM_X4(r0, r1, r2, r3, a) \
    asm volatile("ldmatrix.sync.aligned.m8n8.x4.shared.b16 {%0,%1,%2,%3}, [%4];" \
                 : "=r"(r0), "=r"(r1), "=r"(r2), "=r"(r3) : "r"(a))
#define LDSM_X2_T(r0, r1, a) \
    asm volatile("ldmatrix.sync.aligned.m8n8.x2.trans.shared.b16 {%0,%1}, [%2];" \
                 : "=r"(r0), "=r"(r1) : "r"(a))
// D(f32 4) += A(bf16 16x16) * B(bf16 16x8 col)
#define MMA16816(d, a, b0, b1) \
    asm volatile("mma.sync.aligned.m16n8k16.row.col.f32.bf16.bf16.f32 " \
                 "{%0,%1,%2,%3}, {%4,%5,%6,%7}, {%8,%9}, {%0,%1,%2,%3};" \
                 : "+f"((d)[0]), "+f"((d)[1]), "+f"((d)[2]), "+f"((d)[3]) \
                 : "r"((a)[0]), "r"((a)[1]), "r"((a)[2]), "r"((a)[3]), "r"(b0), "r"(b1))

// ============================================================================
// proj v3 (HMMA, bf16 hi/lo 3-product): 512 threads, 16 warps,
// warp tile = 16 rows x 64 cols (4 warps/SMSP for latency hiding).
// ============================================================================
#define PJ_ROWB 144
#define PJ_AH 0
#define PJ_AL 18432
#define PJ_BH 36864
#define PJ_BL 55296
#define PJ_SA 73728
#define PJ_SB 106496
#define PJ_SSR 139264            // float[2][128] ss partials
#define PJ_SMEM (PJ_SSR + 1024)

__global__ __launch_bounds__(512, 1)
void proj_hmma_kernel(const float* __restrict__ x,
                      const float* __restrict__ Wqk, const float* __restrict__ bqk,
                      const float* __restrict__ Wv,  const float* __restrict__ bv) {
    extern __shared__ char smem[];
    const uint32_t sb = smem_to_u32(smem);
    float* ssred = (float*)(smem + PJ_SSR);
    const int tid = threadIdx.x, wid = tid >> 5, lane = tid & 31;
    const int g = wid & 7, hf = wid >> 3;
    const int row0 = blockIdx.x * 128;
    const int type = blockIdx.y;
    const float* W = type ? Wv : Wqk;
    const float* bias = type ? bv : bqk;

    const int rA = ((lane >> 3) & 1) * 8 + (lane & 7);
    const int kA = (lane >> 4) & 1;
    const int rB = ((lane >> 4) & 1) * 8 + (lane & 7);
    const int kB = (lane >> 3) & 1;
    const int qr = lane >> 2, c2 = lane & 3;

    float acc[8][4];
#pragma unroll
    for (int f = 0; f < 8; f++)
#pragma unroll
        for (int q = 0; q < 4; q++) acc[f][q] = 0.f;

    // preload chunk 0 (fp32 staging)
#pragma unroll
    for (int it = 0; it < 4; it++) {
        int idx = it * 512 + tid;
        int r = idx >> 4, kq = (idx & 15) * 4;
        cp16(sb + PJ_SA + r * 256 + kq * 4, &x[(size_t)(row0 + r) * DIM + kq]);
        cp16(sb + PJ_SB + r * 256 + kq * 4, &W[(size_t)r * DIM + kq]);
    }
    CP_COMMIT();

    for (int c = 0; c < 16; c++) {
        CP_WAIT0();
        __syncthreads();

        // convert fp32 staging -> bf16 hi/lo tiles
#pragma unroll
        for (int it = 0; it < 4; it++) {
            int idx = it * 512 + tid;
            int r = idx >> 4, kq = (idx & 15) * 4;
            float4 fa = *(const float4*)(smem + PJ_SA + r * 256 + kq * 4);
            float4 fb = *(const float4*)(smem + PJ_SB + r * 256 + kq * 4);
            __nv_bfloat162 ah0 = __floats2bfloat162_rn(fa.x, fa.y);
            __nv_bfloat162 ah1 = __floats2bfloat162_rn(fa.z, fa.w);
            __nv_bfloat162 al0 = __floats2bfloat162_rn(fa.x - __bfloat162float(ah0.x),
                                                       fa.y - __bfloat162float(ah0.y));
            __nv_bfloat162 al1 = __floats2bfloat162_rn(fa.z - __bfloat162float(ah1.x),
                                                       fa.w - __bfloat162float(ah1.y));
            __nv_bfloat162 bh0 = __floats2bfloat162_rn(fb.x, fb.y);
            __nv_bfloat162 bh1 = __floats2bfloat162_rn(fb.z, fb.w);
            __nv_bfloat162 bl0 = __floats2bfloat162_rn(fb.x - __bfloat162float(bh0.x),
                                                       fb.y - __bfloat162float(bh0.y));
            __nv_bfloat162 bl1 = __floats2bfloat162_rn(fb.z - __bfloat162float(bh1.x),
                                                       fb.w - __bfloat162float(bh1.y));
            uint2 u;
            u.x = bf2_to_u32(ah0); u.y = bf2_to_u32(ah1);
            *(uint2*)(smem + PJ_AH + r * PJ_ROWB + kq * 2) = u;
            u.x = bf2_to_u32(al0); u.y = bf2_to_u32(al1);
            *(uint2*)(smem + PJ_AL + r * PJ_ROWB + kq * 2) = u;
            u.x = bf2_to_u32(bh0); u.y = bf2_to_u32(bh1);
            *(uint2*)(smem + PJ_BH + r * PJ_ROWB + kq * 2) = u;
            u.x = bf2_to_u32(bl0); u.y = bf2_to_u32(bl1);
            *(uint2*)(smem + PJ_BL + r * PJ_ROWB + kq * 2) = u;
        }
        __syncthreads();

        // prefetch next chunk
        if (c + 1 < 16) {
            const int kk = (c + 1) * 64;
#pragma unroll
            for (int it = 0; it < 4; it++) {
                int idx = it * 512 + tid;
                int r = idx >> 4, kq = (idx & 15) * 4;
                cp16(sb + PJ_SA + r * 256 + kq * 4, &x[(size_t)(row0 + r) * DIM + kk + kq]);
                cp16(sb + PJ_SB + r * 256 + kq * 4, &W[(size_t)r * DIM + kk + kq]);
            }
            CP_COMMIT();
        }

        // A frags for this warp's 16 rows
        uint32_t ah[4][4], al[4][4];
        const uint32_t arh = sb + PJ_AH + (uint32_t)(g * 16 + rA) * PJ_ROWB;
        const uint32_t arl = sb + PJ_AL + (uint32_t)(g * 16 + rA) * PJ_ROWB;
#pragma unroll
        for (int s = 0; s < 4; s++) {
            LDSM_X4(ah[s][0], ah[s][1], ah[s][2], ah[s][3], arh + (s * 16 + kA * 8) * 2);
            LDSM_X4(al[s][0], al[s][1], al[s][2], al[s][3], arl + (s * 16 + kA * 8) * 2);
        }

        // MMA: this warp's 64 cols (ngg = 4*hf + ng)
#pragma unroll
        for (int s = 0; s < 4; s++) {
#pragma unroll
            for (int ng = 0; ng < 4; ng++) {
                const int ngg = 4 * hf + ng;
                uint32_t bh0, bh1, bh2, bh3, bl0, bl1, bl2, bl3;
                const uint32_t boff = (uint32_t)(ngg * 16 + rB) * PJ_ROWB + (s * 16 + kB * 8) * 2;
                LDSM_X4(bh0, bh1, bh2, bh3, sb + PJ_BH + boff);
                LDSM_X4(bl0, bl1, bl2, bl3, sb + PJ_BL + boff);
                MMA16816(acc[2 * ng],     ah[s], bh0, bh1);
                MMA16816(acc[2 * ng + 1], ah[s], bh2, bh3);
                MMA16816(acc[2 * ng],     ah[s], bl0, bl1);
                MMA16816(acc[2 * ng + 1], ah[s], bl2, bl3);
                MMA16816(acc[2 * ng],     al[s], bh0, bh1);
                MMA16816(acc[2 * ng + 1], al[s], bh2, bh3);
            }
        }
    }

    // epilogue
    const int rl = row0 + g * 16 + qr;
    const int rh = rl + 8;
    if (type == 0) {
        float ss0 = 0.f, ss1 = 0.f;
#pragma unroll
        for (int ng = 0; ng < 4; ng++)
#pragma unroll
            for (int j = 0; j < 2; j++) {
                const int f = 2 * ng + j;
                const int col = (4 * hf + ng) * 16 + 8 * j + 2 * c2;
                float2 bb = *(const float2*)&bias[col];
                float c0 = acc[f][0] + bb.x, c1 = acc[f][1] + bb.y;
                float c2v = acc[f][2] + bb.x, c3 = acc[f][3] + bb.y;
                ss0 += c0 * c0 + c1 * c1;
                ss1 += c2v * c2v + c3 * c3;
                *(uint32_t*)&g_qkh[(size_t)rl * DK + col] = bf2_to_u32(__floats2bfloat162_rn(c0, c1));
                *(uint32_t*)&g_qkh[(size_t)rh * DK + col] = bf2_to_u32(__floats2bfloat162_rn(c2v, c3));
            }
        ss0 += __shfl_xor_sync(0xffffffffu, ss0, 1);
        ss0 += __shfl_xor_sync(0xffffffffu, ss0, 2);
        ss1 += __shfl_xor_sync(0xffffffffu, ss1, 1);
        ss1 += __shfl_xor_sync(0xffffffffu, ss1, 2);
        if (c2 == 0) {
            ssred[hf * 128 + g * 16 + qr]     = ss0;
            ssred[hf * 128 + g * 16 + qr + 8] = ss1;
        }
        __syncthreads();
        if (tid < 128) g_ss[row0 + tid] = ssred[tid] + ssred[128 + tid];
    } else {
#pragma unroll
        for (int ng = 0; ng < 4; ng++)
#pragma unroll
            for (int j = 0; j < 2; j++) {
                const int f = 2 * ng + j;
                const int col = (4 * hf + ng) * 16 + 8 * j + 2 * c2;
                float2 bb = *(const float2*)&bias[col];
                float2 v0; v0.x = acc[f][0] + bb.x; v0.y = acc[f][1] + bb.y;
                float2 v1; v1.x = acc[f][2] + bb.x; v1.y = acc[f][3] + bb.y;
                *(float2*)&g_v[(size_t)rl * DV + col] = v0;
                *(float2*)&g_v[(size_t)rh * DV + col] = v1;
            }
    }
}

// ============================================================================
// attention (HMMA): BM=128, 256 thr, split-KV x2, margin 14 — R10 champion
// with ONE change: inactive-tile gate via per-thread partial max +
// __syncthreads_or (full shuffle reduction only inside the active branch).
// ============================================================================
#define ROWB 272
#define AT_K0 0
#define AT_K1 34816
#define AT_VH 69632
#define AT_VL 104448
#define ATT_SMEM (AT_VL + 34816 + 64)

__global__ __launch_bounds__(256, 1)
void attn_kernel() {
    extern __shared__ char smem[];
    const uint32_t sb = smem_to_u32(smem);
    const int tid = threadIdx.x, wid = tid >> 5, lane = tid & 31;
    const int row0 = blockIdx.x * 128;
    const int h = blockIdx.y;
    const int j0base = h * 4096;

    const int rA = ((lane >> 3) & 1) * 8 + (lane & 7);
    const int kA = (lane >> 4) & 1;
    const int rB = ((lane >> 4) & 1) * 8 + (lane & 7);
    const int kB = (lane >> 3) & 1;

    const int rl = row0 + wid * 16 + (lane >> 2);
    const int rh = rl + 8;
    const float m0 = g_ss[rl], m1 = g_ss[rh];
    const float thr0 = m0 - 14.f, thr1 = m1 - 14.f;

#pragma unroll
    for (int it = 0; it < 8; it++) {
        int c = it * 256 + tid;
        int r = c >> 4, cc = (c & 15) * 8;
        cp16(sb + AT_VH + r * ROWB + cc * 2, &g_qkh[(size_t)(row0 + r) * DK + cc]);
        cp16(sb + AT_K0 + r * ROWB + cc * 2, &g_qkh[(size_t)(j0base + r) * DK + cc]);
    }
    CP_COMMIT(); CP_WAIT0();
    __syncthreads();

    uint32_t qa[8][4];
    {
        const uint32_t qrow = sb + AT_VH + (uint32_t)(wid * 16 + rA) * ROWB;
#pragma unroll
        for (int s = 0; s < 8; s++)
            LDSM_X4(qa[s][0], qa[s][1], qa[s][2], qa[s][3], qrow + (s * 16 + kA * 8) * 2);
    }
    __syncthreads();   // Q reads done before VH reused for V

    float oa[16][4];
#pragma unroll
    for (int nt = 0; nt < 16; nt++)
#pragma unroll
        for (int q = 0; q < 4; q++) oa[nt][q] = 0.f;
    float l0 = 0.f, l1 = 0.f;

    for (int t = 0; t < 32; t++) {
        if (t > 0) CP_WAIT0();
        __syncthreads();

        if (t + 1 < 32) {
            const uint32_t nb = sb + ((t & 1) ? AT_K0 : AT_K1);
            const int j1 = j0base + (t + 1) * 128;
#pragma unroll
            for (int it = 0; it < 8; it++) {
                int c = it * 256 + tid;
                int r = c >> 4, cc = (c & 15) * 8;
                cp16(nb + r * ROWB + cc * 2, &g_qkh[(size_t)(j1 + r) * DK + cc]);
            }
            CP_COMMIT();
        }

        const uint32_t kb = sb + ((t & 1) ? AT_K1 : AT_K0);
        float sa[16][4];
#pragma unroll
        for (int nt = 0; nt < 16; nt++)
#pragma unroll
            for (int q = 0; q < 4; q++) sa[nt][q] = 0.f;
#pragma unroll
        for (int s = 0; s < 8; s++) {
            const uint32_t kcol = kb + (uint32_t)((s * 16 + kB * 8) * 2);
#pragma unroll
            for (int np = 0; np < 8; np++) {
                uint32_t b0, b1, b2, b3;
                LDSM_X4(b0, b1, b2, b3, kcol + (uint32_t)(np * 16 + rB) * ROWB);
                MMA16816(sa[2 * np],     qa[s], b0, b1);
                MMA16816(sa[2 * np + 1], qa[s], b2, b3);
            }
        }

        // per-thread partial row maxes (exact detection: the lane holding a
        // row's peak fires the predicate)
        float mx0 = -3.0e38f, mx1 = -3.0e38f;
#pragma unroll
        for (int nt = 0; nt < 16; nt++) {
            mx0 = fmaxf(mx0, fmaxf(sa[nt][0], sa[nt][1]));
            mx1 = fmaxf(mx1, fmaxf(sa[nt][2], sa[nt][3]));
        }
        const int cact = __syncthreads_or((mx0 >= thr0) || (mx1 >= thr1));

        if (cact) {
            // exact row maxes + act flags (only when some row in CTA is active)
            mx0 = fmaxf(mx0, __shfl_xor_sync(0xffffffffu, mx0, 1));
            mx0 = fmaxf(mx0, __shfl_xor_sync(0xffffffffu, mx0, 2));
            mx1 = fmaxf(mx1, __shfl_xor_sync(0xffffffffu, mx1, 1));
            mx1 = fmaxf(mx1, __shfl_xor_sync(0xffffffffu, mx1, 2));
            const bool act0 = mx0 >= thr0, act1 = mx1 >= thr1;
            const int wact = __any_sync(0xffffffffu, act0 || act1);

            const int j0 = j0base + t * 128;
#pragma unroll
            for (int it = 0; it < 16; it++) {
                int idx = it * 256 + tid;
                int r = idx >> 5, cq = (idx & 31) * 4;
                float4 f = *(const float4*)&g_v[(size_t)(j0 + r) * DV + cq];
                __nv_bfloat162 h0 = __floats2bfloat162_rn(f.x, f.y);
                __nv_bfloat162 h1 = __floats2bfloat162_rn(f.z, f.w);
                __nv_bfloat162 e0 = __floats2bfloat162_rn(f.x - __bfloat162float(h0.x),
                                                          f.y - __bfloat162float(h0.y));
                __nv_bfloat162 e1 = __floats2bfloat162_rn(f.z - __bfloat162float(h1.x),
                                                          f.w - __bfloat162float(h1.y));
                uint2 uh; uh.x = bf2_to_u32(h0); uh.y = bf2_to_u32(h1);
                uint2 ul; ul.x = bf2_to_u32(e0); ul.y = bf2_to_u32(e1);
                *(uint2*)(smem + AT_VH + r * ROWB + cq * 2) = uh;
                *(uint2*)(smem + AT_VL + r * ROWB + cq * 2) = ul;
            }
            __syncthreads();

            if (wact) {
#pragma unroll
                for (int s = 0; s < 8; s++) {
                    uint32_t pa[4];
                    float e00 = act0 ? __expf(sa[2 * s][0] - m0) : 0.f;
                    float e01 = act0 ? __expf(sa[2 * s][1] - m0) : 0.f;
                    float e10 = act1 ? __expf(sa[2 * s][2] - m1) : 0.f;
                    float e11 = act1 ? __expf(sa[2 * s][3] - m1) : 0.f;
                    float f00 = act0 ? __expf(sa[2 * s + 1][0] - m0) : 0.f;
                    float f01 = act0 ? __expf(sa[2 * s + 1][1] - m0) : 0.f;
                    float f10 = act1 ? __expf(sa[2 * s + 1][2] - m1) : 0.f;
                    float f11 = act1 ? __expf(sa[2 * s + 1][3] - m1) : 0.f;
                    __nv_bfloat162 b;
                    b = __floats2bfloat162_rn(e00, e01); pa[0] = bf2_to_u32(b);
                    l0 += __bfloat162float(b.x) + __bfloat162float(b.y);
                    b = __floats2bfloat162_rn(e10, e11); pa[1] = bf2_to_u32(b);
                    l1 += __bfloat162float(b.x) + __bfloat162float(b.y);
                    b = __floats2bfloat162_rn(f00, f01); pa[2] = bf2_to_u32(b);
                    l0 += __bfloat162float(b.x) + __bfloat162float(b.y);
                    b = __floats2bfloat162_rn(f10, f11); pa[3] = bf2_to_u32(b);
                    l1 += __bfloat162float(b.x) + __bfloat162float(b.y);

                    const uint32_t vrow = (uint32_t)(s * 16 + rA) * ROWB;
#pragma unroll
                    for (int nt = 0; nt < 16; nt++) {
                        uint32_t bh0, bh1;
                        LDSM_X2_T(bh0, bh1, sb + AT_VH + vrow + nt * 16);
                        MMA16816(oa[nt], pa, bh0, bh1);
                    }
#pragma unroll
                    for (int nt = 0; nt < 16; nt++) {
                        uint32_t bl0, bl1;
                        LDSM_X2_T(bl0, bl1, sb + AT_VL + vrow + nt * 16);
                        MMA16816(oa[nt], pa, bl0, bl1);
                    }
                }
            }
        }
    }

    l0 += __shfl_xor_sync(0xffffffffu, l0, 1);
    l0 += __shfl_xor_sync(0xffffffffu, l0, 2);
    l1 += __shfl_xor_sync(0xffffffffu, l1, 1);
    l1 += __shfl_xor_sync(0xffffffffu, l1, 2);
#pragma unroll
    for (int nt = 0; nt < 16; nt++) {
        const int col = nt * 8 + 2 * (lane & 3);
        float2 v0; v0.x = oa[nt][0]; v0.y = oa[nt][1];
        float2 v1; v1.x = oa[nt][2]; v1.y = oa[nt][3];
        *(float2*)&g_O[h][(size_t)rl * DV + col] = v0;
        *(float2*)&g_O[h][(size_t)rh * DV + col] = v1;
    }
    if ((lane & 3) == 0) {
        g_l[h][rl] = l0;
        g_l[h][rh] = l1;
    }
}

// ============================================================================
// combine v2: 4 float4/thread for MLP (grid 256)
// ============================================================================
__global__ __launch_bounds__(256, 4)
void combine_kernel(float* __restrict__ out) {
    const int base = blockIdx.x * 1024 + threadIdx.x;
#pragma unroll
    for (int j = 0; j < 4; j++) {
        const int i4 = base + j * 256;
        const int rowi = i4 >> 5;
        const float inv = 1.0f / (g_l[0][rowi] + g_l[1][rowi]);
        float4 a = ((const float4*)g_O[0])[i4];
        float4 b = ((const float4*)g_O[1])[i4];
        float4 o = make_float4((a.x + b.x) * inv, (a.y + b.y) * inv,
                               (a.z + b.z) * inv, (a.w + b.w) * inv);
        ((float4*)out)[i4] = o;
    }
}

// ---------------------------------------------------------------------------
extern "C" void kernel_launch(void* const* d_in, const int* in_sizes, int n_in,
                              void* d_out, int out_size) {
    const float* x   = (const float*)d_in[0];
    const float* Wqk = (const float*)d_in[1];
    const float* bqk = (const float*)d_in[2];
    const float* Wv  = (const float*)d_in[3];
    const float* bv  = (const float*)d_in[4];
    float* out = (float*)d_out;

    cudaFuncSetAttribute(proj_hmma_kernel, cudaFuncAttributeMaxDynamicSharedMemorySize, PJ_SMEM);
    cudaFuncSetAttribute(attn_kernel, cudaFuncAttributeMaxDynamicSharedMemorySize, ATT_SMEM);

    proj_hmma_kernel<<<dim3(NTOK / 128, 2), 512, PJ_SMEM>>>(x, Wqk, bqk, Wv, bv);
    attn_kernel<<<dim3(NTOK / 128, 2), 256, ATT_SMEM>>>();
    combine_kernel<<<256, 256>>>(out);
}

// round 15
// speedup vs baseline: 1.2483x; 1.2483x over previous
#include <cuda_runtime.h>
#include <cuda_bf16.h>
#include <stdint.h>

#define NTOK 8192
#define DIM  1024
#define DK   128
#define DV   128

// ---------------- device globals (allocation-free scratch) ----------------
__device__ float g_v[NTOK * DV];
__device__ __align__(256) __nv_bfloat16 g_qkh[NTOK * DK];   // qk bf16 row-major
__device__ __align__(256) float g_ss[NTOK];                 // ||qk_i||^2 fp32
__device__ __align__(256) float g_O[NTOK * DV];             // numerators (atomic)
__device__ __align__(256) float g_l[NTOK];                  // denominators (atomic)

// ---------------- helpers ----------------
__device__ __forceinline__ uint32_t smem_to_u32(const void* p) {
    uint32_t a;
    asm("{ .reg .u64 t; cvta.to.shared.u64 t, %1; cvt.u32.u64 %0, t; }" : "=r"(a) : "l"(p));
    return a;
}
__device__ __forceinline__ void cp16(uint32_t dst, const void* src) {
    asm volatile("cp.async.cg.shared.global [%0], [%1], 16;" :: "r"(dst), "l"(src) : "memory");
}
#define CP_COMMIT() asm volatile("cp.async.commit_group;" ::: "memory")
#define CP_WAIT0()  asm volatile("cp.async.wait_group 0;" ::: "memory")

__device__ __forceinline__ uint32_t bf2_to_u32(__nv_bfloat162 v) {
    uint32_t u; *(__nv_bfloat162*)&u = v; return u;
}

#define LDSM_X4(r0, r1, r2, r3, a) \
    asm volatile("ldmatrix.sync.aligned.m8n8.x4.shared.b16 {%0,%1,%2,%3}, [%4];" \
                 : "=r"(r0), "=r"(r1), "=r"(r2), "=r"(r3) : "r"(a))
#define LDSM_X2_T(r0, r1, a) \
    asm volatile("ldmatrix.sync.aligned.m8n8.x2.trans.shared.b16 {%0,%1}, [%2];" \
                 : "=r"(r0), "=r"(r1) : "r"(a))
#define MMA16816(d, a, b0, b1) \
    asm volatile("mma.sync.aligned.m16n8k16.row.col.f32.bf16.bf16.f32 " \
                 "{%0,%1,%2,%3}, {%4,%5,%6,%7}, {%8,%9}, {%0,%1,%2,%3};" \
                 : "+f"((d)[0]), "+f"((d)[1]), "+f"((d)[2]), "+f"((d)[3]) \
                 : "r"((a)[0]), "r"((a)[1]), "r"((a)[2]), "r"((a)[3]), "r"(b0), "r"(b1))

// ============================================================================
// proj v3 (HMMA, bf16 hi/lo 3-product): 512 threads — R14, proven, verbatim
// ============================================================================
#define PJ_ROWB 144
#define PJ_AH 0
#define PJ_AL 18432
#define PJ_BH 36864
#define PJ_BL 55296
#define PJ_SA 73728
#define PJ_SB 106496
#define PJ_SSR 139264
#define PJ_SMEM (PJ_SSR + 1024)

__global__ __launch_bounds__(512, 1)
void proj_hmma_kernel(const float* __restrict__ x,
                      const float* __restrict__ Wqk, const float* __restrict__ bqk,
                      const float* __restrict__ Wv,  const float* __restrict__ bv) {
    extern __shared__ char smem[];
    const uint32_t sb = smem_to_u32(smem);
    float* ssred = (float*)(smem + PJ_SSR);
    const int tid = threadIdx.x, wid = tid >> 5, lane = tid & 31;
    const int g = wid & 7, hf = wid >> 3;
    const int row0 = blockIdx.x * 128;
    const int type = blockIdx.y;
    const float* W = type ? Wv : Wqk;
    const float* bias = type ? bv : bqk;

    const int rA = ((lane >> 3) & 1) * 8 + (lane & 7);
    const int kA = (lane >> 4) & 1;
    const int rB = ((lane >> 4) & 1) * 8 + (lane & 7);
    const int kB = (lane >> 3) & 1;
    const int qr = lane >> 2, c2 = lane & 3;

    float acc[8][4];
#pragma unroll
    for (int f = 0; f < 8; f++)
#pragma unroll
        for (int q = 0; q < 4; q++) acc[f][q] = 0.f;

#pragma unroll
    for (int it = 0; it < 4; it++) {
        int idx = it * 512 + tid;
        int r = idx >> 4, kq = (idx & 15) * 4;
        cp16(sb + PJ_SA + r * 256 + kq * 4, &x[(size_t)(row0 + r) * DIM + kq]);
        cp16(sb + PJ_SB + r * 256 + kq * 4, &W[(size_t)r * DIM + kq]);
    }
    CP_COMMIT();

    for (int c = 0; c < 16; c++) {
        CP_WAIT0();
        __syncthreads();

#pragma unroll
        for (int it = 0; it < 4; it++) {
            int idx = it * 512 + tid;
            int r = idx >> 4, kq = (idx & 15) * 4;
            float4 fa = *(const float4*)(smem + PJ_SA + r * 256 + kq * 4);
            float4 fb = *(const float4*)(smem + PJ_SB + r * 256 + kq * 4);
            __nv_bfloat162 ah0 = __floats2bfloat162_rn(fa.x, fa.y);
            __nv_bfloat162 ah1 = __floats2bfloat162_rn(fa.z, fa.w);
            __nv_bfloat162 al0 = __floats2bfloat162_rn(fa.x - __bfloat162float(ah0.x),
                                                       fa.y - __bfloat162float(ah0.y));
            __nv_bfloat162 al1 = __floats2bfloat162_rn(fa.z - __bfloat162float(ah1.x),
                                                       fa.w - __bfloat162float(ah1.y));
            __nv_bfloat162 bh0 = __floats2bfloat162_rn(fb.x, fb.y);
            __nv_bfloat162 bh1 = __floats2bfloat162_rn(fb.z, fb.w);
            __nv_bfloat162 bl0 = __floats2bfloat162_rn(fb.x - __bfloat162float(bh0.x),
                                                       fb.y - __bfloat162float(bh0.y));
            __nv_bfloat162 bl1 = __floats2bfloat162_rn(fb.z - __bfloat162float(bh1.x),
                                                       fb.w - __bfloat162float(bh1.y));
            uint2 u;
            u.x = bf2_to_u32(ah0); u.y = bf2_to_u32(ah1);
            *(uint2*)(smem + PJ_AH + r * PJ_ROWB + kq * 2) = u;
            u.x = bf2_to_u32(al0); u.y = bf2_to_u32(al1);
            *(uint2*)(smem + PJ_AL + r * PJ_ROWB + kq * 2) = u;
            u.x = bf2_to_u32(bh0); u.y = bf2_to_u32(bh1);
            *(uint2*)(smem + PJ_BH + r * PJ_ROWB + kq * 2) = u;
            u.x = bf2_to_u32(bl0); u.y = bf2_to_u32(bl1);
            *(uint2*)(smem + PJ_BL + r * PJ_ROWB + kq * 2) = u;
        }
        __syncthreads();

        if (c + 1 < 16) {
            const int kk = (c + 1) * 64;
#pragma unroll
            for (int it = 0; it < 4; it++) {
                int idx = it * 512 + tid;
                int r = idx >> 4, kq = (idx & 15) * 4;
                cp16(sb + PJ_SA + r * 256 + kq * 4, &x[(size_t)(row0 + r) * DIM + kk + kq]);
                cp16(sb + PJ_SB + r * 256 + kq * 4, &W[(size_t)r * DIM + kk + kq]);
            }
            CP_COMMIT();
        }

        uint32_t ah[4][4], al[4][4];
        const uint32_t arh = sb + PJ_AH + (uint32_t)(g * 16 + rA) * PJ_ROWB;
        const uint32_t arl = sb + PJ_AL + (uint32_t)(g * 16 + rA) * PJ_ROWB;
#pragma unroll
        for (int s = 0; s < 4; s++) {
            LDSM_X4(ah[s][0], ah[s][1], ah[s][2], ah[s][3], arh + (s * 16 + kA * 8) * 2);
            LDSM_X4(al[s][0], al[s][1], al[s][2], al[s][3], arl + (s * 16 + kA * 8) * 2);
        }

#pragma unroll
        for (int s = 0; s < 4; s++) {
#pragma unroll
            for (int ng = 0; ng < 4; ng++) {
                const int ngg = 4 * hf + ng;
                uint32_t bh0, bh1, bh2, bh3, bl0, bl1, bl2, bl3;
                const uint32_t boff = (uint32_t)(ngg * 16 + rB) * PJ_ROWB + (s * 16 + kB * 8) * 2;
                LDSM_X4(bh0, bh1, bh2, bh3, sb + PJ_BH + boff);
                LDSM_X4(bl0, bl1, bl2, bl3, sb + PJ_BL + boff);
                MMA16816(acc[2 * ng],     ah[s], bh0, bh1);
                MMA16816(acc[2 * ng + 1], ah[s], bh2, bh3);
                MMA16816(acc[2 * ng],     ah[s], bl0, bl1);
                MMA16816(acc[2 * ng + 1], ah[s], bl2, bl3);
                MMA16816(acc[2 * ng],     al[s], bh0, bh1);
                MMA16816(acc[2 * ng + 1], al[s], bh2, bh3);
            }
        }
    }

    const int rl = row0 + g * 16 + qr;
    const int rh = rl + 8;
    if (type == 0) {
        float ss0 = 0.f, ss1 = 0.f;
#pragma unroll
        for (int ng = 0; ng < 4; ng++)
#pragma unroll
            for (int j = 0; j < 2; j++) {
                const int f = 2 * ng + j;
                const int col = (4 * hf + ng) * 16 + 8 * j + 2 * c2;
                float2 bb = *(const float2*)&bias[col];
                float c0 = acc[f][0] + bb.x, c1 = acc[f][1] + bb.y;
                float c2v = acc[f][2] + bb.x, c3 = acc[f][3] + bb.y;
                ss0 += c0 * c0 + c1 * c1;
                ss1 += c2v * c2v + c3 * c3;
                *(uint32_t*)&g_qkh[(size_t)rl * DK + col] = bf2_to_u32(__floats2bfloat162_rn(c0, c1));
                *(uint32_t*)&g_qkh[(size_t)rh * DK + col] = bf2_to_u32(__floats2bfloat162_rn(c2v, c3));
            }
        ss0 += __shfl_xor_sync(0xffffffffu, ss0, 1);
        ss0 += __shfl_xor_sync(0xffffffffu, ss0, 2);
        ss1 += __shfl_xor_sync(0xffffffffu, ss1, 1);
        ss1 += __shfl_xor_sync(0xffffffffu, ss1, 2);
        if (c2 == 0) {
            ssred[hf * 128 + g * 16 + qr]     = ss0;
            ssred[hf * 128 + g * 16 + qr + 8] = ss1;
        }
        __syncthreads();
        if (tid < 128) g_ss[row0 + tid] = ssred[tid] + ssred[128 + tid];
    } else {
#pragma unroll
        for (int ng = 0; ng < 4; ng++)
#pragma unroll
            for (int j = 0; j < 2; j++) {
                const int f = 2 * ng + j;
                const int col = (4 * hf + ng) * 16 + 8 * j + 2 * c2;
                float2 bb = *(const float2*)&bias[col];
                float2 v0; v0.x = acc[f][0] + bb.x; v0.y = acc[f][1] + bb.y;
                float2 v1; v1.x = acc[f][2] + bb.x; v1.y = acc[f][3] + bb.y;
                *(float2*)&g_v[(size_t)rl * DV + col] = v0;
                *(float2*)&g_v[(size_t)rh * DV + col] = v1;
            }
    }
}

// ============================================================================
// zero_kernel: clear g_O + g_l before atomic accumulation
// ============================================================================
__global__ __launch_bounds__(256, 4)
void zero_kernel() {
    const int i4 = blockIdx.x * 256 + threadIdx.x;   // 262144 float4s
    ((float4*)g_O)[i4] = make_float4(0.f, 0.f, 0.f, 0.f);
    if (blockIdx.x < 32) g_l[blockIdx.x * 256 + threadIdx.x] = 0.f;
}

// ============================================================================
// attn_sym: one CTA per unordered pair (bi <= bj) of 128-row blocks.
// S computed ONCE per pair; screened both directions (margin 14);
// contributions accumulated atomically into g_O/g_l.
// smem: B0 = Q tile -> PT (direction-B P), B1 = K tile -> V-hi, B2 = V-lo.
// ============================================================================
#define ROWB 272
#define SB0 0
#define SB1 34816
#define SB2 69632
#define SM_THRJ 104448
#define SM_MJ   104960
#define SM_SLB  105472
#define ATT_SMEM 105984

__global__ __launch_bounds__(256, 2)
void attn_kernel() {
    const int bi = blockIdx.x, bj = blockIdx.y;
    if (bj < bi) return;
    const int diag = (bi == bj);
    const int gI = bi * 128, gJ = bj * 128;

    extern __shared__ char smem[];
    const uint32_t sb = smem_to_u32(smem);
    float* thrJ = (float*)(smem + SM_THRJ);
    float* mJ   = (float*)(smem + SM_MJ);
    float* slB  = (float*)(smem + SM_SLB);
    const int tid = threadIdx.x, wid = tid >> 5, lane = tid & 31;

    const int rA = ((lane >> 3) & 1) * 8 + (lane & 7);
    const int kA = (lane >> 4) & 1;
    const int rB = ((lane >> 4) & 1) * 8 + (lane & 7);
    const int kB = (lane >> 3) & 1;
    const int qr = lane >> 2, c2 = lane & 3;

    const int rlL = wid * 16 + qr, rhL = rlL + 8;
    const float m0 = g_ss[gI + rlL], m1 = g_ss[gI + rhL];
    const float thr0 = m0 - 14.f, thr1 = m1 - 14.f;

    // load Q (rows I) -> B0, K (rows J) -> B1; thrJ/mJ/slB init
#pragma unroll
    for (int it = 0; it < 8; it++) {
        int c = it * 256 + tid;
        int r = c >> 4, cc = (c & 15) * 8;
        cp16(sb + SB0 + r * ROWB + cc * 2, &g_qkh[(size_t)(gI + r) * DK + cc]);
        cp16(sb + SB1 + r * ROWB + cc * 2, &g_qkh[(size_t)(gJ + r) * DK + cc]);
    }
    if (tid < 128) {
        float s = g_ss[gJ + tid];
        thrJ[tid] = s - 14.f;
        mJ[tid] = s;
        slB[tid] = 0.f;
    }
    CP_COMMIT(); CP_WAIT0();
    __syncthreads();

    // Q A-frags
    uint32_t qa[8][4];
    {
        const uint32_t qrow = sb + SB0 + (uint32_t)(wid * 16 + rA) * ROWB;
#pragma unroll
        for (int s = 0; s < 8; s++)
            LDSM_X4(qa[s][0], qa[s][1], qa[s][2], qa[s][3], qrow + (s * 16 + kA * 8) * 2);
    }

    // S = Q_I K_J^T
    float sa[16][4];
#pragma unroll
    for (int nt = 0; nt < 16; nt++)
#pragma unroll
        for (int q = 0; q < 4; q++) sa[nt][q] = 0.f;
#pragma unroll
    for (int s = 0; s < 8; s++) {
        const uint32_t kcol = sb + SB1 + (uint32_t)((s * 16 + kB * 8) * 2);
#pragma unroll
        for (int np = 0; np < 8; np++) {
            uint32_t b0, b1, b2, b3;
            LDSM_X4(b0, b1, b2, b3, kcol + (uint32_t)(np * 16 + rB) * ROWB);
            MMA16816(sa[2 * np],     qa[s], b0, b1);
            MMA16816(sa[2 * np + 1], qa[s], b2, b3);
        }
    }

    // screen both directions
    float mx0 = -3.0e38f, mx1 = -3.0e38f;
#pragma unroll
    for (int nt = 0; nt < 16; nt++) {
        mx0 = fmaxf(mx0, fmaxf(sa[nt][0], sa[nt][1]));
        mx1 = fmaxf(mx1, fmaxf(sa[nt][2], sa[nt][3]));
    }
    int pred = ((mx0 >= thr0) || (mx1 >= thr1)) ? 1 : 0;
    if (!diag) {
        int pb = 0;
#pragma unroll
        for (int nt = 0; nt < 16; nt++) {
            const int col = nt * 8 + 2 * c2;
            float2 tj = *(const float2*)&thrJ[col];
            pb |= (sa[nt][0] >= tj.x) | (sa[nt][1] >= tj.y) |
                  (sa[nt][2] >= tj.x) | (sa[nt][3] >= tj.y);
        }
        if (pb) pred |= 2;
    }
    const int act = __syncthreads_or(pred);
    if (!act) return;

    // direction-B: write PT = exp(S - m_col) transposed into B0, accumulate slB
    if (act & 2) {
#pragma unroll
        for (int nt = 0; nt < 16; nt++) {
            const int col = nt * 8 + 2 * c2;
            float2 mj2 = *(const float2*)&mJ[col];
            __nv_bfloat16 b00 = __float2bfloat16_rn(__expf(sa[nt][0] - mj2.x));
            __nv_bfloat16 b01 = __float2bfloat16_rn(__expf(sa[nt][1] - mj2.y));
            __nv_bfloat16 b10 = __float2bfloat16_rn(__expf(sa[nt][2] - mj2.x));
            __nv_bfloat16 b11 = __float2bfloat16_rn(__expf(sa[nt][3] - mj2.y));
            *(__nv_bfloat16*)(smem + SB0 + col * ROWB + rlL * 2) = b00;
            *(__nv_bfloat16*)(smem + SB0 + (col + 1) * ROWB + rlL * 2) = b01;
            *(__nv_bfloat16*)(smem + SB0 + col * ROWB + rhL * 2) = b10;
            *(__nv_bfloat16*)(smem + SB0 + (col + 1) * ROWB + rhL * 2) = b11;
            atomicAdd(&slB[col],     __bfloat162float(b00) + __bfloat162float(b10));
            atomicAdd(&slB[col + 1], __bfloat162float(b01) + __bfloat162float(b11));
        }
    }

    // direction-A: rows I over keys J
    if (act & 1) {
        // V[J] hi/lo into B1/B2 (K reads finished at the or-barrier)
#pragma unroll
        for (int it = 0; it < 16; it++) {
            int idx = it * 256 + tid;
            int r = idx >> 5, cq = (idx & 31) * 4;
            float4 f = *(const float4*)&g_v[(size_t)(gJ + r) * DV + cq];
            __nv_bfloat162 h0 = __floats2bfloat162_rn(f.x, f.y);
            __nv_bfloat162 h1 = __floats2bfloat162_rn(f.z, f.w);
            __nv_bfloat162 e0 = __floats2bfloat162_rn(f.x - __bfloat162float(h0.x),
                                                      f.y - __bfloat162float(h0.y));
            __nv_bfloat162 e1 = __floats2bfloat162_rn(f.z - __bfloat162float(h1.x),
                                                      f.w - __bfloat162float(h1.y));
            uint2 uh; uh.x = bf2_to_u32(h0); uh.y = bf2_to_u32(h1);
            uint2 ul; ul.x = bf2_to_u32(e0); ul.y = bf2_to_u32(e1);
            *(uint2*)(smem + SB1 + r * ROWB + cq * 2) = uh;
            *(uint2*)(smem + SB2 + r * ROWB + cq * 2) = ul;
        }
        __syncthreads();

        float oa[16][4];
#pragma unroll
        for (int nt = 0; nt < 16; nt++)
#pragma unroll
            for (int q = 0; q < 4; q++) oa[nt][q] = 0.f;
        float l0 = 0.f, l1 = 0.f;

#pragma unroll
        for (int s = 0; s < 8; s++) {
            uint32_t pa[4];
            __nv_bfloat162 b;
            b = __floats2bfloat162_rn(__expf(sa[2 * s][0] - m0), __expf(sa[2 * s][1] - m0));
            pa[0] = bf2_to_u32(b); l0 += __bfloat162float(b.x) + __bfloat162float(b.y);
            b = __floats2bfloat162_rn(__expf(sa[2 * s][2] - m1), __expf(sa[2 * s][3] - m1));
            pa[1] = bf2_to_u32(b); l1 += __bfloat162float(b.x) + __bfloat162float(b.y);
            b = __floats2bfloat162_rn(__expf(sa[2 * s + 1][0] - m0), __expf(sa[2 * s + 1][1] - m0));
            pa[2] = bf2_to_u32(b); l0 += __bfloat162float(b.x) + __bfloat162float(b.y);
            b = __floats2bfloat162_rn(__expf(sa[2 * s + 1][2] - m1), __expf(sa[2 * s + 1][3] - m1));
            pa[3] = bf2_to_u32(b); l1 += __bfloat162float(b.x) + __bfloat162float(b.y);

            const uint32_t vrow = (uint32_t)(s * 16 + rA) * ROWB;
#pragma unroll
            for (int nt = 0; nt < 16; nt++) {
                uint32_t bh0, bh1;
                LDSM_X2_T(bh0, bh1, sb + SB1 + vrow + nt * 16);
                MMA16816(oa[nt], pa, bh0, bh1);
            }
#pragma unroll
            for (int nt = 0; nt < 16; nt++) {
                uint32_t bl0, bl1;
                LDSM_X2_T(bl0, bl1, sb + SB2 + vrow + nt * 16);
                MMA16816(oa[nt], pa, bl0, bl1);
            }
        }
        // flush A
#pragma unroll
        for (int nt = 0; nt < 16; nt++) {
            const int col = nt * 8 + 2 * c2;
            atomicAdd(&g_O[(size_t)(gI + rlL) * DV + col],     oa[nt][0]);
            atomicAdd(&g_O[(size_t)(gI + rlL) * DV + col + 1], oa[nt][1]);
            atomicAdd(&g_O[(size_t)(gI + rhL) * DV + col],     oa[nt][2]);
            atomicAdd(&g_O[(size_t)(gI + rhL) * DV + col + 1], oa[nt][3]);
        }
        l0 += __shfl_xor_sync(0xffffffffu, l0, 1);
        l0 += __shfl_xor_sync(0xffffffffu, l0, 2);
        l1 += __shfl_xor_sync(0xffffffffu, l1, 1);
        l1 += __shfl_xor_sync(0xffffffffu, l1, 2);
        if (c2 == 0) {
            atomicAdd(&g_l[gI + rlL], l0);
            atomicAdd(&g_l[gI + rhL], l1);
        }
    }

    // direction-B: rows J over keys I (P from PT in B0)
    if (act & 2) {
        __syncthreads();   // PT/slB visible; PV-A reads of B1/B2 done
        // V[I] hi/lo into B1/B2
#pragma unroll
        for (int it = 0; it < 16; it++) {
            int idx = it * 256 + tid;
            int r = idx >> 5, cq = (idx & 31) * 4;
            float4 f = *(const float4*)&g_v[(size_t)(gI + r) * DV + cq];
            __nv_bfloat162 h0 = __floats2bfloat162_rn(f.x, f.y);
            __nv_bfloat162 h1 = __floats2bfloat162_rn(f.z, f.w);
            __nv_bfloat162 e0 = __floats2bfloat162_rn(f.x - __bfloat162float(h0.x),
                                                      f.y - __bfloat162float(h0.y));
            __nv_bfloat162 e1 = __floats2bfloat162_rn(f.z - __bfloat162float(h1.x),
                                                      f.w - __bfloat162float(h1.y));
            uint2 uh; uh.x = bf2_to_u32(h0); uh.y = bf2_to_u32(h1);
            uint2 ul; ul.x = bf2_to_u32(e0); ul.y = bf2_to_u32(e1);
            *(uint2*)(smem + SB1 + r * ROWB + cq * 2) = uh;
            *(uint2*)(smem + SB2 + r * ROWB + cq * 2) = ul;
        }
        __syncthreads();

        float oa[16][4];
#pragma unroll
        for (int nt = 0; nt < 16; nt++)
#pragma unroll
            for (int q = 0; q < 4; q++) oa[nt][q] = 0.f;

        const uint32_t prow = sb + SB0 + (uint32_t)(wid * 16 + rA) * ROWB;
#pragma unroll
        for (int s = 0; s < 8; s++) {
            uint32_t pa[4];
            LDSM_X4(pa[0], pa[1], pa[2], pa[3], prow + (s * 16 + kA * 8) * 2);
            const uint32_t vrow = (uint32_t)(s * 16 + rA) * ROWB;
#pragma unroll
            for (int nt = 0; nt < 16; nt++) {
                uint32_t bh0, bh1;
                LDSM_X2_T(bh0, bh1, sb + SB1 + vrow + nt * 16);
                MMA16816(oa[nt], pa, bh0, bh1);
            }
#pragma unroll
            for (int nt = 0; nt < 16; nt++) {
                uint32_t bl0, bl1;
                LDSM_X2_T(bl0, bl1, sb + SB2 + vrow + nt * 16);
                MMA16816(oa[nt], pa, bl0, bl1);
            }
        }
        // flush B
#pragma unroll
        for (int nt = 0; nt < 16; nt++) {
            const int col = nt * 8 + 2 * c2;
            atomicAdd(&g_O[(size_t)(gJ + rlL) * DV + col],     oa[nt][0]);
            atomicAdd(&g_O[(size_t)(gJ + rlL) * DV + col + 1], oa[nt][1]);
            atomicAdd(&g_O[(size_t)(gJ + rhL) * DV + col],     oa[nt][2]);
            atomicAdd(&g_O[(size_t)(gJ + rhL) * DV + col + 1], oa[nt][3]);
        }
        if (tid < 128) atomicAdd(&g_l[gJ + tid], slB[tid]);
    }
}

// ============================================================================
// combine: out = O / l
// ============================================================================
__global__ __launch_bounds__(256, 4)
void combine_kernel(float* __restrict__ out) {
    const int base = blockIdx.x * 1024 + threadIdx.x;
#pragma unroll
    for (int j = 0; j < 4; j++) {
        const int i4 = base + j * 256;
        const float inv = 1.0f / g_l[i4 >> 5];
        float4 a = ((const float4*)g_O)[i4];
        float4 o = make_float4(a.x * inv, a.y * inv, a.z * inv, a.w * inv);
        ((float4*)out)[i4] = o;
    }
}

// ---------------------------------------------------------------------------
extern "C" void kernel_launch(void* const* d_in, const int* in_sizes, int n_in,
                              void* d_out, int out_size) {
    const float* x   = (const float*)d_in[0];
    const float* Wqk = (const float*)d_in[1];
    const float* bqk = (const float*)d_in[2];
    const float* Wv  = (const float*)d_in[3];
    const float* bv  = (const float*)d_in[4];
    float* out = (float*)d_out;

    cudaFuncSetAttribute(proj_hmma_kernel, cudaFuncAttributeMaxDynamicSharedMemorySize, PJ_SMEM);
    cudaFuncSetAttribute(attn_kernel, cudaFuncAttributeMaxDynamicSharedMemorySize, ATT_SMEM);

    zero_kernel<<<1024, 256>>>();
    proj_hmma_kernel<<<dim3(NTOK / 128, 2), 512, PJ_SMEM>>>(x, Wqk, bqk, Wv, bv);
    attn_kernel<<<dim3(64, 64), 256, ATT_SMEM>>>();
    combine_kernel<<<256, 256>>>(out);
}